// round 12
// baseline (speedup 1.0000x reference)
#include <cuda_runtime.h>
#include <cuda_bf16.h>
#include <cstdint>

// NCEAverage: out[b,k] = exp(dot(memory[idx'[b,k]], x[b]) / T) / Z
// idx'[b,0] = y[b];  Z = mean(out_unnorm) * N
// B=256, K=4096, D=128, N=1e6, T=0.07
//
// Phase-partitioned gather, 8 phases WITH pacing: 512 blocks (single
// resident wave) bucket their 2048 row indices by row>>17 and sweep the
// slices in lockstep — __syncthreads between phases keeps warps together,
// and a soft chip-wide gate (block spins until >= NBLK-64 blocks finished
// the previous phase) bounds drift so the ~42MB unique-row slice stays
// L2-resident. Deadlock-free: all blocks co-resident, gate is cumulative.
// Scores staged in SMEM, flushed with plain stores (out stays L2-resident
// for the norm kernel). Z: ticket + last-block fixed-order double reduce.

#define B_SZ 256
#define K_SZ 4096
#define D_SZ 128
#define N_SZ 1000000
#define INV_T (1.0f / 0.07f)

#define TPB 256
#define WARPS 8
#define KRANGE 2048                    // k's per block
#define NBLK (B_SZ * K_SZ / KRANGE)    // 512 blocks = one resident wave
#define EPT (KRANGE / TPB)             // 8 indices per thread
#define PHASE_SHIFT 17                 // 8 phases of <=131072 rows (~67MB)
#define NPH 8
#define GATE_SLACK 64                  // start p+1 when NBLK-64 finished p

__device__ float        g_partials[NBLK];
__device__ float        g_scale;
__device__ unsigned int g_ticket;      // zero-init; last block resets
__device__ volatile unsigned int g_phase_done[NPH];  // zero-init; last block resets

__global__ __launch_bounds__(TPB, 4)
void nce_scores_kernel(const float* __restrict__ x,
                       const int* __restrict__ y,
                       const int* __restrict__ idx,
                       const float* __restrict__ memory,
                       float* __restrict__ out) {
    __shared__ uint32_t           entries[KRANGE];   // (row<<11)|k_local
    __shared__ float              sout[KRANGE];      // staged scores
    __shared__ unsigned long long wtotA[WARPS];
    __shared__ unsigned long long wtotB[WARPS];
    __shared__ float              ssum[WARPS];
    __shared__ double             dsh[TPB];
    __shared__ bool               s_last;

    const int t     = threadIdx.x;
    const int lane  = t & 31;
    const int warp  = t >> 5;
    const int o     = lane & 7;        // octet within row
    const int r     = lane >> 3;       // which of 4 rows in a group
    const int b     = blockIdx.x >> 1;
    const int kbase = (blockIdx.x & 1) * KRANGE;

    // ---- 1. Load indices, count per phase (thread-major canonical order) ----
    const int* idx_b = idx + (size_t)b * K_SZ + kbase;
    uint32_t myrow[EPT];
    uint32_t cnt[NPH];
    #pragma unroll
    for (int p = 0; p < NPH; p++) cnt[p] = 0;
    #pragma unroll
    for (int j = 0; j < EPT; j++) {
        const int kl = j * TPB + t;
        const uint32_t row = (uint32_t)((kbase + kl == 0) ? y[b] : idx_b[kl]);
        myrow[j] = row;
        cnt[row >> PHASE_SHIFT] += 1u;
    }

    // ---- 2. Dual packed scans (phases 0-3 / 4-7), warp shfl + cross-warp ----
    unsigned long long vA = (unsigned long long)cnt[0]
                          | ((unsigned long long)cnt[1] << 16)
                          | ((unsigned long long)cnt[2] << 32)
                          | ((unsigned long long)cnt[3] << 48);
    unsigned long long vB = (unsigned long long)cnt[4]
                          | ((unsigned long long)cnt[5] << 16)
                          | ((unsigned long long)cnt[6] << 32)
                          | ((unsigned long long)cnt[7] << 48);
    unsigned long long wsA = vA, wsB = vB;
    #pragma unroll
    for (int off = 1; off < 32; off <<= 1) {
        const unsigned long long nA = __shfl_up_sync(0xffffffffu, wsA, off);
        const unsigned long long nB = __shfl_up_sync(0xffffffffu, wsB, off);
        if (lane >= off) { wsA += nA; wsB += nB; }
    }
    if (lane == 31) { wtotA[warp] = wsA; wtotB[warp] = wsB; }
    __syncthreads();
    unsigned long long preA = 0, preB = 0, totA = 0, totB = 0;
    #pragma unroll
    for (int w = 0; w < WARPS; w++) {
        const unsigned long long a = wtotA[w], bb = wtotB[w];
        if (w < warp) { preA += a; preB += bb; }
        totA += a; totB += bb;
    }
    const unsigned long long exA = wsA + preA - vA;
    const unsigned long long exB = wsB + preB - vB;

    uint32_t tc[NPH];
    #pragma unroll
    for (int p = 0; p < 4; p++) {
        tc[p]     = (uint32_t)(totA >> (16 * p)) & 0xffffu;
        tc[p + 4] = (uint32_t)(totB >> (16 * p)) & 0xffffu;
    }
    uint32_t pos[NPH];
    {
        uint32_t base = 0;
        #pragma unroll
        for (int p = 0; p < NPH; p++) {
            const uint32_t ex = (p < 4)
                ? ((uint32_t)(exA >> (16 * p))       & 0xffffu)
                : ((uint32_t)(exB >> (16 * (p - 4))) & 0xffffu);
            pos[p] = base + ex;
            base += tc[p];
        }
    }

    // ---- 3. Deterministic scatter into phase buckets ----
    #pragma unroll
    for (int j = 0; j < EPT; j++) {
        const uint32_t row = myrow[j];
        const uint32_t p   = row >> PHASE_SHIFT;
        const uint32_t ent = (row << 11) | (uint32_t)(j * TPB + t);
        entries[pos[p]++] = ent;
    }
    __syncthreads();

    // ---- 4. Gather + dot + exp, phase by phase, paced chip-wide ----
    const float4* x4 = reinterpret_cast<const float4*>(x + b * D_SZ);
    const float4 xx0 = x4[0 * 8 + o];
    const float4 xx1 = x4[1 * 8 + o];
    const float4 xx2 = x4[2 * 8 + o];
    const float4 xx3 = x4[3 * 8 + o];

    float wsum = 0.0f;
    uint32_t lo = 0;
    #pragma unroll 1
    for (int p = 0; p < NPH; p++) {
        const uint32_t hi = lo + tc[p];
        for (uint32_t e0 = lo + (uint32_t)warp * 4u; e0 < hi; e0 += WARPS * 4u) {
            const uint32_t e = e0 + (uint32_t)r;
            const bool valid = (e < hi);
            float acc = 0.0f;
            uint32_t kl = 0;
            if (valid) {
                const uint32_t ent = entries[e];
                const uint32_t row = ent >> 11;
                kl = ent & 2047u;
                const float4* m4 = reinterpret_cast<const float4*>(memory + (size_t)row * D_SZ);
                const float4 w0 = m4[0 * 8 + o];
                const float4 w1 = m4[1 * 8 + o];
                const float4 w2 = m4[2 * 8 + o];
                const float4 w3 = m4[3 * 8 + o];
                acc  = w0.x * xx0.x + w0.y * xx0.y + w0.z * xx0.z + w0.w * xx0.w;
                acc += w1.x * xx1.x + w1.y * xx1.y + w1.z * xx1.z + w1.w * xx1.w;
                acc += w2.x * xx2.x + w2.y * xx2.y + w2.z * xx2.z + w2.w * xx2.w;
                acc += w3.x * xx3.x + w3.y * xx3.y + w3.z * xx3.z + w3.w * xx3.w;
            }
            // converge, then reduce the 8 lanes of each row (4 rows at once)
            acc += __shfl_xor_sync(0xffffffffu, acc, 1);
            acc += __shfl_xor_sync(0xffffffffu, acc, 2);
            acc += __shfl_xor_sync(0xffffffffu, acc, 4);
            if (o == 0 && valid) {
                const float s = __expf(acc * INV_T);
                sout[kl] = s;
                wsum += s;
            }
        }
        lo = hi;

        // Phase gate: keep the chip's slice sweep aligned. All 512 blocks
        // are co-resident -> cumulative counter always reaches threshold.
        __syncthreads();
        if (t == 0) {
            __threadfence();
            atomicAdd((unsigned int*)&g_phase_done[p], 1u);
            if (p < NPH - 1) {
                while (g_phase_done[p] < (unsigned int)(NBLK - GATE_SLACK))
                    __nanosleep(128);
            }
        }
        __syncthreads();
    }

    // ---- 5. Coalesced flush (plain stores: keep `out` L2-resident) ----
    float4* ob4 = reinterpret_cast<float4*>(out + (size_t)b * K_SZ + kbase);
    const float4* so4 = reinterpret_cast<const float4*>(sout);
    #pragma unroll
    for (int i = 0; i < KRANGE / 4 / TPB; i++)      // 2 iterations
        ob4[t + i * TPB] = so4[t + i * TPB];

    // ---- 6. Block partial (fixed order) + ticket ----
    #pragma unroll
    for (int s = 16; s > 0; s >>= 1)
        wsum += __shfl_xor_sync(0xffffffffu, wsum, s);
    if (lane == 0) ssum[warp] = wsum;
    __syncthreads();
    if (t == 0) {
        float acc = 0.0f;
        #pragma unroll
        for (int w = 0; w < WARPS; w++) acc += ssum[w];
        g_partials[blockIdx.x] = acc;
        __threadfence();
        const unsigned int tk = atomicAdd(&g_ticket, 1u);
        s_last = (tk == NBLK - 1);
    }
    __syncthreads();

    // ---- 7. Last block: fixed-order double reduce + counter resets ----
    if (s_last) {
        double acc = (double)g_partials[t] + (double)g_partials[t + TPB];
        dsh[t] = acc;
        __syncthreads();
        for (int s = TPB / 2; s > 0; s >>= 1) {
            if (t < s) dsh[t] += dsh[t + s];
            __syncthreads();
        }
        if (t == 0) {
            // Z = (sum / (B*K)) * N ; scale = 1/Z — double avoids fp32
            // overflow (sum ~ 1e31; sum*N would be inf in fp32).
            const double sum = dsh[0];
            g_scale = (float)(((double)B_SZ * (double)K_SZ) /
                              (sum * (double)N_SZ));
            g_ticket = 0u;             // reset for graph replay
            #pragma unroll
            for (int p = 0; p < NPH; p++) g_phase_done[p] = 0u;
            __threadfence();
        }
    }
}

// out: 262144 float4s -> 1024 blocks x 256 threads x 1 float4.
// Reads hit L2 (scores flushed plain); writes stream out.
__global__ __launch_bounds__(256)
void nce_norm_kernel(float* __restrict__ out) {
    const float s = g_scale;
    const int i = blockIdx.x * blockDim.x + threadIdx.x;
    float4* o = reinterpret_cast<float4*>(out);
    float4 v = o[i];
    v.x *= s; v.y *= s; v.z *= s; v.w *= s;
    __stcs(&o[i], v);
}

extern "C" void kernel_launch(void* const* d_in, const int* in_sizes, int n_in,
                              void* d_out, int out_size) {
    const float* x      = (const float*)d_in[0];
    const int*   y      = (const int*)d_in[1];
    const int*   idx    = (const int*)d_in[2];
    const float* memory = (const float*)d_in[3];
    float* out = (float*)d_out;

    nce_scores_kernel<<<NBLK, TPB>>>(x, y, idx, memory, out);
    const int nvec4 = (B_SZ * K_SZ) / 4;   // 262144
    nce_norm_kernel<<<nvec4 / 256, 256>>>(out);
}

// round 13
// speedup vs baseline: 1.0589x; 1.0589x over previous
#include <cuda_runtime.h>
#include <cuda_bf16.h>
#include <cstdint>

// NCEAverage: out[b,k] = exp(dot(memory[idx'[b,k]], x[b]) / T) / Z
// idx'[b,0] = y[b];  Z = mean(out_unnorm) * N
// B=256, K=4096, D=128, N=1e6, T=0.07
//
// Phase-partitioned gather (4 phases, FREE-RUNNING — pacing/gating loses):
// 1024 blocks (single resident wave, ~7/SM = 56 warps/SM for latency cover)
// each own one (b, 1024-k) range and deterministically bucket their row
// indices by row>>18; the chip sweeps slices roughly together so duplicate
// rows hit L2 instead of DRAM. Scores staged in SMEM, flushed with plain
// stores (out stays L2-resident for the norm kernel).
// Z: ticket + last-block fixed-order double reduce (deterministic).

#define B_SZ 256
#define K_SZ 4096
#define D_SZ 128
#define N_SZ 1000000
#define INV_T (1.0f / 0.07f)

#define TPB 256
#define WARPS 8
#define KRANGE 1024                    // k's per block
#define NBLK (B_SZ * K_SZ / KRANGE)    // 1024 blocks = one resident wave
#define EPT (KRANGE / TPB)             // 4 indices per thread
#define PHASE_SHIFT 18                 // 4 phases of <=262144 rows (~134MB)

__device__ float        g_partials[NBLK];
__device__ float        g_scale;
__device__ unsigned int g_ticket;      // zero-init; last block resets

__global__ __launch_bounds__(TPB, 8)
void nce_scores_kernel(const float* __restrict__ x,
                       const int* __restrict__ y,
                       const int* __restrict__ idx,
                       const float* __restrict__ memory,
                       float* __restrict__ out) {
    __shared__ uint32_t           entries[KRANGE];   // (row<<11)|k_local
    __shared__ float              sout[KRANGE];      // staged scores
    __shared__ unsigned long long wtot[WARPS];
    __shared__ float              ssum[WARPS];
    __shared__ double             dsh[TPB];
    __shared__ bool               s_last;

    const int t     = threadIdx.x;
    const int lane  = t & 31;
    const int warp  = t >> 5;
    const int o     = lane & 7;        // octet within row
    const int r     = lane >> 3;       // which of 4 rows in a group
    const int b     = blockIdx.x >> 2;                 // 4 blocks per b
    const int kbase = (blockIdx.x & 3) * KRANGE;

    // ---- 1. Load indices, count per phase (thread-major canonical order) ----
    const int* idx_b = idx + (size_t)b * K_SZ + kbase;
    uint32_t myrow[EPT];
    uint32_t c0 = 0, c1 = 0, c2 = 0, c3 = 0;
    #pragma unroll
    for (int j = 0; j < EPT; j++) {
        const int kl = j * TPB + t;
        const uint32_t row = (uint32_t)((kbase + kl == 0) ? y[b] : idx_b[kl]);
        myrow[j] = row;
        const uint32_t p = row >> PHASE_SHIFT;
        c0 += (p == 0); c1 += (p == 1); c2 += (p == 2); c3 += (p == 3);
    }

    // ---- 2. Scan of 4x16-bit packed counts: warp shfl scan + cross-warp ----
    const unsigned long long v = (unsigned long long)c0
                               | ((unsigned long long)c1 << 16)
                               | ((unsigned long long)c2 << 32)
                               | ((unsigned long long)c3 << 48);
    unsigned long long ws = v;                       // warp-inclusive scan
    #pragma unroll
    for (int off = 1; off < 32; off <<= 1) {
        const unsigned long long n = __shfl_up_sync(0xffffffffu, ws, off);
        if (lane >= off) ws += n;
    }
    if (lane == 31) wtot[warp] = ws;
    __syncthreads();
    unsigned long long wpre = 0, tot = 0;
    #pragma unroll
    for (int w = 0; w < WARPS; w++) {               // fixed order, tiny
        const unsigned long long wv = wtot[w];
        if (w < warp) wpre += wv;
        tot += wv;
    }
    const unsigned long long incl = ws + wpre;
    const unsigned long long excl = incl - v;

    const uint32_t t0 = (uint32_t)(tot      ) & 0xffffu;
    const uint32_t t1 = (uint32_t)(tot >> 16) & 0xffffu;
    const uint32_t t2 = (uint32_t)(tot >> 32) & 0xffffu;
    const uint32_t t3 = (uint32_t)(tot >> 48) & 0xffffu;

    uint32_t pos0 =                ((uint32_t)(excl      ) & 0xffffu);
    uint32_t pos1 = t0           + ((uint32_t)(excl >> 16) & 0xffffu);
    uint32_t pos2 = t0 + t1      + ((uint32_t)(excl >> 32) & 0xffffu);
    uint32_t pos3 = t0 + t1 + t2 + ((uint32_t)(excl >> 48) & 0xffffu);

    // ---- 3. Deterministic scatter into phase buckets ----
    #pragma unroll
    for (int j = 0; j < EPT; j++) {
        const uint32_t row = myrow[j];
        const uint32_t p   = row >> PHASE_SHIFT;
        const uint32_t ent = (row << 11) | (uint32_t)(j * TPB + t);
        uint32_t pp;
        if      (p == 0) pp = pos0++;
        else if (p == 1) pp = pos1++;
        else if (p == 2) pp = pos2++;
        else             pp = pos3++;
        entries[pp] = ent;
    }
    __syncthreads();

    // ---- 4. Gather + dot + exp, phase by phase (free-running) ----
    const float4* x4 = reinterpret_cast<const float4*>(x + b * D_SZ);
    const float4 xx0 = x4[0 * 8 + o];
    const float4 xx1 = x4[1 * 8 + o];
    const float4 xx2 = x4[2 * 8 + o];
    const float4 xx3 = x4[3 * 8 + o];

    const uint32_t tc[4] = { t0, t1, t2, t3 };
    float wsum = 0.0f;
    uint32_t lo = 0;
    #pragma unroll
    for (int p = 0; p < 4; p++) {
        const uint32_t hi = lo + tc[p];
        for (uint32_t e0 = lo + (uint32_t)warp * 4u; e0 < hi; e0 += WARPS * 4u) {
            const uint32_t e = e0 + (uint32_t)r;
            const bool valid = (e < hi);
            float acc = 0.0f;
            uint32_t kl = 0;
            if (valid) {
                const uint32_t ent = entries[e];
                const uint32_t row = ent >> 11;
                kl = ent & 2047u;
                const float4* m4 = reinterpret_cast<const float4*>(memory + (size_t)row * D_SZ);
                const float4 w0 = m4[0 * 8 + o];
                const float4 w1 = m4[1 * 8 + o];
                const float4 w2 = m4[2 * 8 + o];
                const float4 w3 = m4[3 * 8 + o];
                acc  = w0.x * xx0.x + w0.y * xx0.y + w0.z * xx0.z + w0.w * xx0.w;
                acc += w1.x * xx1.x + w1.y * xx1.y + w1.z * xx1.z + w1.w * xx1.w;
                acc += w2.x * xx2.x + w2.y * xx2.y + w2.z * xx2.z + w2.w * xx2.w;
                acc += w3.x * xx3.x + w3.y * xx3.y + w3.z * xx3.z + w3.w * xx3.w;
            }
            // converge, then reduce the 8 lanes of each row (4 rows at once)
            acc += __shfl_xor_sync(0xffffffffu, acc, 1);
            acc += __shfl_xor_sync(0xffffffffu, acc, 2);
            acc += __shfl_xor_sync(0xffffffffu, acc, 4);
            if (o == 0 && valid) {
                const float s = __expf(acc * INV_T);
                sout[kl] = s;
                wsum += s;
            }
        }
        lo = hi;
    }

    // ---- 5. Coalesced flush (plain stores: keep `out` L2-resident) ----
    __syncthreads();
    float4* ob4 = reinterpret_cast<float4*>(out + (size_t)b * K_SZ + kbase);
    const float4* so4 = reinterpret_cast<const float4*>(sout);
    ob4[t] = so4[t];                                 // KRANGE/4 == TPB

    // ---- 6. Block partial (fixed order) + ticket ----
    #pragma unroll
    for (int s = 16; s > 0; s >>= 1)
        wsum += __shfl_xor_sync(0xffffffffu, wsum, s);
    if (lane == 0) ssum[warp] = wsum;
    __syncthreads();
    if (t == 0) {
        float acc = 0.0f;
        #pragma unroll
        for (int w = 0; w < WARPS; w++) acc += ssum[w];
        g_partials[blockIdx.x] = acc;
        __threadfence();
        const unsigned int tk = atomicAdd(&g_ticket, 1u);
        s_last = (tk == NBLK - 1);
    }
    __syncthreads();

    // ---- 7. Last block: fixed-order double reduce of 1024 partials ----
    if (s_last) {
        double acc = 0.0;
        #pragma unroll
        for (int j = 0; j < NBLK / TPB; j++)         // 4 iterations
            acc += (double)g_partials[t + j * TPB];
        dsh[t] = acc;
        __syncthreads();
        for (int s = TPB / 2; s > 0; s >>= 1) {
            if (t < s) dsh[t] += dsh[t + s];
            __syncthreads();
        }
        if (t == 0) {
            // Z = (sum / (B*K)) * N ; scale = 1/Z — double avoids fp32
            // overflow (sum ~ 1e31; sum*N would be inf in fp32).
            const double sum = dsh[0];
            g_scale = (float)(((double)B_SZ * (double)K_SZ) /
                              (sum * (double)N_SZ));
            g_ticket = 0u;             // reset for graph replay
            __threadfence();
        }
    }
}

// out: 262144 float4s -> 1024 blocks x 256 threads x 1 float4.
// Reads hit L2 (scores flushed plain); writes stream out.
__global__ __launch_bounds__(256)
void nce_norm_kernel(float* __restrict__ out) {
    const float s = g_scale;
    const int i = blockIdx.x * blockDim.x + threadIdx.x;
    float4* o = reinterpret_cast<float4*>(out);
    float4 v = o[i];
    v.x *= s; v.y *= s; v.z *= s; v.w *= s;
    __stcs(&o[i], v);
}

extern "C" void kernel_launch(void* const* d_in, const int* in_sizes, int n_in,
                              void* d_out, int out_size) {
    const float* x      = (const float*)d_in[0];
    const int*   y      = (const int*)d_in[1];
    const int*   idx    = (const int*)d_in[2];
    const float* memory = (const float*)d_in[3];
    float* out = (float*)d_out;

    nce_scores_kernel<<<NBLK, TPB>>>(x, y, idx, memory, out);
    const int nvec4 = (B_SZ * K_SZ) / 4;   // 262144
    nce_norm_kernel<<<nvec4 / 256, 256>>>(out);
}

// round 14
// speedup vs baseline: 1.2606x; 1.1905x over previous
#include <cuda_runtime.h>
#include <cuda_bf16.h>
#include <cstdint>

// NCEAverage: out[b,k] = exp(dot(memory[idx'[b,k]], x[b]) / T) / Z
// idx'[b,0] = y[b];  Z = mean(out_unnorm) * N
// B=256, K=4096, D=128, N=1e6, T=0.07
//
// Phase-partitioned gather, 6 phases, FREE-RUNNING (no gates — any chip-wide
// pacing between DRAM-bound phases loses; measured twice). 512 blocks
// (single resident wave) each own one (b, 2048-k) range and deterministically
// bucket their 2048 row indices by phase = (row*6)>>20 (~87MB slice, ~54MB
// unique-touched: two drift-adjacent slices fit the 126MB L2 together, unlike
// the 4-phase 134MB slices). Duplicate rows hit L2 instead of DRAM.
// Scores staged in SMEM, flushed with plain stores (out stays L2-resident
// for the norm kernel). Z: ticket + last-block fixed-order double reduce.

#define B_SZ 256
#define K_SZ 4096
#define D_SZ 128
#define N_SZ 1000000
#define INV_T (1.0f / 0.07f)

#define TPB 256
#define WARPS 8
#define KRANGE 2048                    // k's per block
#define NBLK (B_SZ * K_SZ / KRANGE)    // 512 blocks = one resident wave
#define EPT (KRANGE / TPB)             // 8 indices per thread
#define NPH 6                          // phase = (row*6)>>20

__device__ float        g_partials[NBLK];
__device__ float        g_scale;
__device__ unsigned int g_ticket;      // zero-init; last block resets

__global__ __launch_bounds__(TPB, 4)
void nce_scores_kernel(const float* __restrict__ x,
                       const int* __restrict__ y,
                       const int* __restrict__ idx,
                       const float* __restrict__ memory,
                       float* __restrict__ out) {
    __shared__ uint32_t           entries[KRANGE];   // (row<<11)|k_local
    __shared__ float              sout[KRANGE];      // staged scores
    __shared__ unsigned long long wtotA[WARPS];
    __shared__ unsigned long long wtotB[WARPS];
    __shared__ float              ssum[WARPS];
    __shared__ double             dsh[TPB];
    __shared__ bool               s_last;

    const int t     = threadIdx.x;
    const int lane  = t & 31;
    const int warp  = t >> 5;
    const int o     = lane & 7;        // octet within row
    const int r     = lane >> 3;       // which of 4 rows in a group
    const int b     = blockIdx.x >> 1;
    const int kbase = (blockIdx.x & 1) * KRANGE;

    // ---- 1. Load indices, count per phase (thread-major canonical order) ----
    const int* idx_b = idx + (size_t)b * K_SZ + kbase;
    uint32_t myrow[EPT];
    uint32_t cnt[NPH];
    #pragma unroll
    for (int p = 0; p < NPH; p++) cnt[p] = 0;
    #pragma unroll
    for (int j = 0; j < EPT; j++) {
        const int kl = j * TPB + t;
        const uint32_t row = (uint32_t)((kbase + kl == 0) ? y[b] : idx_b[kl]);
        myrow[j] = row;
        cnt[(row * 6u) >> 20] += 1u;   // exact 6-way split, N < 2^20
    }

    // ---- 2. Dual packed scans (phases 0-3 / 4-5): warp shfl + cross-warp ----
    const unsigned long long vA = (unsigned long long)cnt[0]
                                | ((unsigned long long)cnt[1] << 16)
                                | ((unsigned long long)cnt[2] << 32)
                                | ((unsigned long long)cnt[3] << 48);
    const unsigned long long vB = (unsigned long long)cnt[4]
                                | ((unsigned long long)cnt[5] << 16);
    unsigned long long wsA = vA, wsB = vB;
    #pragma unroll
    for (int off = 1; off < 32; off <<= 1) {
        const unsigned long long nA = __shfl_up_sync(0xffffffffu, wsA, off);
        const unsigned long long nB = __shfl_up_sync(0xffffffffu, wsB, off);
        if (lane >= off) { wsA += nA; wsB += nB; }
    }
    if (lane == 31) { wtotA[warp] = wsA; wtotB[warp] = wsB; }
    __syncthreads();
    unsigned long long preA = 0, preB = 0, totA = 0, totB = 0;
    #pragma unroll
    for (int w = 0; w < WARPS; w++) {               // fixed order, tiny
        const unsigned long long a = wtotA[w], bb = wtotB[w];
        if (w < warp) { preA += a; preB += bb; }
        totA += a; totB += bb;
    }
    const unsigned long long exA = wsA + preA - vA;
    const unsigned long long exB = wsB + preB - vB;

    uint32_t tc[NPH];
    #pragma unroll
    for (int p = 0; p < 4; p++) tc[p] = (uint32_t)(totA >> (16 * p)) & 0xffffu;
    tc[4] = (uint32_t)(totB      ) & 0xffffu;
    tc[5] = (uint32_t)(totB >> 16) & 0xffffu;

    uint32_t pos[NPH];
    {
        uint32_t base = 0;
        #pragma unroll
        for (int p = 0; p < NPH; p++) {
            const uint32_t ex = (p < 4)
                ? ((uint32_t)(exA >> (16 * p))       & 0xffffu)
                : ((uint32_t)(exB >> (16 * (p - 4))) & 0xffffu);
            pos[p] = base + ex;
            base += tc[p];
        }
    }

    // ---- 3. Deterministic scatter into phase buckets ----
    #pragma unroll
    for (int j = 0; j < EPT; j++) {
        const uint32_t row = myrow[j];
        const uint32_t p   = (row * 6u) >> 20;
        const uint32_t ent = (row << 11) | (uint32_t)(j * TPB + t);
        entries[pos[p]++] = ent;
    }
    __syncthreads();

    // ---- 4. Gather + dot + exp, phase by phase (free-running) ----
    const float4* x4 = reinterpret_cast<const float4*>(x + b * D_SZ);
    const float4 xx0 = x4[0 * 8 + o];
    const float4 xx1 = x4[1 * 8 + o];
    const float4 xx2 = x4[2 * 8 + o];
    const float4 xx3 = x4[3 * 8 + o];

    float wsum = 0.0f;
    uint32_t lo = 0;
    #pragma unroll 1
    for (int p = 0; p < NPH; p++) {
        const uint32_t hi = lo + tc[p];
        for (uint32_t e0 = lo + (uint32_t)warp * 4u; e0 < hi; e0 += WARPS * 4u) {
            const uint32_t e = e0 + (uint32_t)r;
            const bool valid = (e < hi);
            float acc = 0.0f;
            uint32_t kl = 0;
            if (valid) {
                const uint32_t ent = entries[e];
                const uint32_t row = ent >> 11;
                kl = ent & 2047u;
                const float4* m4 = reinterpret_cast<const float4*>(memory + (size_t)row * D_SZ);
                const float4 w0 = m4[0 * 8 + o];
                const float4 w1 = m4[1 * 8 + o];
                const float4 w2 = m4[2 * 8 + o];
                const float4 w3 = m4[3 * 8 + o];
                acc  = w0.x * xx0.x + w0.y * xx0.y + w0.z * xx0.z + w0.w * xx0.w;
                acc += w1.x * xx1.x + w1.y * xx1.y + w1.z * xx1.z + w1.w * xx1.w;
                acc += w2.x * xx2.x + w2.y * xx2.y + w2.z * xx2.z + w2.w * xx2.w;
                acc += w3.x * xx3.x + w3.y * xx3.y + w3.z * xx3.z + w3.w * xx3.w;
            }
            // converge, then reduce the 8 lanes of each row (4 rows at once)
            acc += __shfl_xor_sync(0xffffffffu, acc, 1);
            acc += __shfl_xor_sync(0xffffffffu, acc, 2);
            acc += __shfl_xor_sync(0xffffffffu, acc, 4);
            if (o == 0 && valid) {
                const float s = __expf(acc * INV_T);
                sout[kl] = s;
                wsum += s;
            }
        }
        lo = hi;
    }

    // ---- 5. Coalesced flush (plain stores: keep `out` L2-resident) ----
    __syncthreads();
    float4* ob4 = reinterpret_cast<float4*>(out + (size_t)b * K_SZ + kbase);
    const float4* so4 = reinterpret_cast<const float4*>(sout);
    #pragma unroll
    for (int i = 0; i < KRANGE / 4 / TPB; i++)      // 2 iterations
        ob4[t + i * TPB] = so4[t + i * TPB];

    // ---- 6. Block partial (fixed order) + ticket ----
    #pragma unroll
    for (int s = 16; s > 0; s >>= 1)
        wsum += __shfl_xor_sync(0xffffffffu, wsum, s);
    if (lane == 0) ssum[warp] = wsum;
    __syncthreads();
    if (t == 0) {
        float acc = 0.0f;
        #pragma unroll
        for (int w = 0; w < WARPS; w++) acc += ssum[w];
        g_partials[blockIdx.x] = acc;
        __threadfence();
        const unsigned int tk = atomicAdd(&g_ticket, 1u);
        s_last = (tk == NBLK - 1);
    }
    __syncthreads();

    // ---- 7. Last block: fixed-order double reduce of 512 partials ----
    if (s_last) {
        double acc = (double)g_partials[t] + (double)g_partials[t + TPB];
        dsh[t] = acc;
        __syncthreads();
        for (int s = TPB / 2; s > 0; s >>= 1) {
            if (t < s) dsh[t] += dsh[t + s];
            __syncthreads();
        }
        if (t == 0) {
            // Z = (sum / (B*K)) * N ; scale = 1/Z — double avoids fp32
            // overflow (sum ~ 1e31; sum*N would be inf in fp32).
            const double sum = dsh[0];
            g_scale = (float)(((double)B_SZ * (double)K_SZ) /
                              (sum * (double)N_SZ));
            g_ticket = 0u;             // reset for graph replay
            __threadfence();
        }
    }
}

// out: 262144 float4s -> 1024 blocks x 256 threads x 1 float4.
// Reads hit L2 (scores flushed plain); writes stream out.
__global__ __launch_bounds__(256)
void nce_norm_kernel(float* __restrict__ out) {
    const float s = g_scale;
    const int i = blockIdx.x * blockDim.x + threadIdx.x;
    float4* o = reinterpret_cast<float4*>(out);
    float4 v = o[i];
    v.x *= s; v.y *= s; v.z *= s; v.w *= s;
    __stcs(&o[i], v);
}

extern "C" void kernel_launch(void* const* d_in, const int* in_sizes, int n_in,
                              void* d_out, int out_size) {
    const float* x      = (const float*)d_in[0];
    const int*   y      = (const int*)d_in[1];
    const int*   idx    = (const int*)d_in[2];
    const float* memory = (const float*)d_in[3];
    float* out = (float*)d_out;

    nce_scores_kernel<<<NBLK, TPB>>>(x, y, idx, memory, out);
    const int nvec4 = (B_SZ * K_SZ) / 4;   // 262144
    nce_norm_kernel<<<nvec4 / 256, 256>>>(out);
}

// round 15
// speedup vs baseline: 1.3269x; 1.0526x over previous
#include <cuda_runtime.h>
#include <cuda_bf16.h>
#include <cstdint>

// NCEAverage: out[b,k] = exp(dot(memory[idx'[b,k]], x[b]) / T) / Z
// idx'[b,0] = y[b];  Z = mean(out_unnorm) * N
// B=256, K=4096, D=128, N=1e6, T=0.07
//
// Phase-partitioned gather, 3 phases, FREE-RUNNING (pacing loses, measured
// twice; phase-count curve: 4->72.2us, 6->76.3, 8->80.2 — fewer phases churn
// slower and tolerate drift better; 3 is the last untested point, its
// unique-touched set ~111MB still fits the 126MB L2). 512 blocks (single
// resident wave) each own one (b, 2048-k) range, deterministically bucket
// their 2048 row indices by phase=(row*3)>>20, and sweep slices together so
// duplicate rows hit L2 instead of DRAM. Scores staged in SMEM, flushed with
// plain stores (out stays L2-resident for the norm kernel).
// Z: ticket + last-block fixed-order double reduce (deterministic).

#define B_SZ 256
#define K_SZ 4096
#define D_SZ 128
#define N_SZ 1000000
#define INV_T (1.0f / 0.07f)

#define TPB 256
#define WARPS 8
#define KRANGE 2048                    // k's per block
#define NBLK (B_SZ * K_SZ / KRANGE)    // 512 blocks = one resident wave
#define EPT (KRANGE / TPB)             // 8 indices per thread
#define NPH 3                          // phase = (row*3)>>20

__device__ float        g_partials[NBLK];
__device__ float        g_scale;
__device__ unsigned int g_ticket;      // zero-init; last block resets

__global__ __launch_bounds__(TPB, 4)
void nce_scores_kernel(const float* __restrict__ x,
                       const int* __restrict__ y,
                       const int* __restrict__ idx,
                       const float* __restrict__ memory,
                       float* __restrict__ out) {
    __shared__ uint32_t           entries[KRANGE];   // (row<<11)|k_local
    __shared__ float              sout[KRANGE];      // staged scores
    __shared__ unsigned long long wtot[WARPS];
    __shared__ float              ssum[WARPS];
    __shared__ double             dsh[TPB];
    __shared__ bool               s_last;

    const int t     = threadIdx.x;
    const int lane  = t & 31;
    const int warp  = t >> 5;
    const int o     = lane & 7;        // octet within row
    const int r     = lane >> 3;       // which of 4 rows in a group
    const int b     = blockIdx.x >> 1;
    const int kbase = (blockIdx.x & 1) * KRANGE;

    // ---- 1. Load indices, count per phase (thread-major canonical order) ----
    const int* idx_b = idx + (size_t)b * K_SZ + kbase;
    uint32_t myrow[EPT];
    uint32_t c0 = 0, c1 = 0, c2 = 0;
    #pragma unroll
    for (int j = 0; j < EPT; j++) {
        const int kl = j * TPB + t;
        const uint32_t row = (uint32_t)((kbase + kl == 0) ? y[b] : idx_b[kl]);
        myrow[j] = row;
        const uint32_t p = (row * 3u) >> 20;   // exact 3-way split, N < 2^20
        c0 += (p == 0); c1 += (p == 1); c2 += (p == 2);
    }

    // ---- 2. Packed scan (3x16-bit counts): warp shfl scan + cross-warp ----
    const unsigned long long v = (unsigned long long)c0
                               | ((unsigned long long)c1 << 16)
                               | ((unsigned long long)c2 << 32);
    unsigned long long ws = v;                       // warp-inclusive scan
    #pragma unroll
    for (int off = 1; off < 32; off <<= 1) {
        const unsigned long long n = __shfl_up_sync(0xffffffffu, ws, off);
        if (lane >= off) ws += n;
    }
    if (lane == 31) wtot[warp] = ws;
    __syncthreads();
    unsigned long long wpre = 0, tot = 0;
    #pragma unroll
    for (int w = 0; w < WARPS; w++) {               // fixed order, tiny
        const unsigned long long wv = wtot[w];
        if (w < warp) wpre += wv;
        tot += wv;
    }
    const unsigned long long excl = ws + wpre - v;

    const uint32_t t0 = (uint32_t)(tot      ) & 0xffffu;
    const uint32_t t1 = (uint32_t)(tot >> 16) & 0xffffu;
    const uint32_t t2 = (uint32_t)(tot >> 32) & 0xffffu;

    uint32_t pos0 =           ((uint32_t)(excl      ) & 0xffffu);
    uint32_t pos1 = t0      + ((uint32_t)(excl >> 16) & 0xffffu);
    uint32_t pos2 = t0 + t1 + ((uint32_t)(excl >> 32) & 0xffffu);

    // ---- 3. Deterministic scatter into phase buckets ----
    #pragma unroll
    for (int j = 0; j < EPT; j++) {
        const uint32_t row = myrow[j];
        const uint32_t p   = (row * 3u) >> 20;
        const uint32_t ent = (row << 11) | (uint32_t)(j * TPB + t);
        uint32_t pp;
        if      (p == 0) pp = pos0++;
        else if (p == 1) pp = pos1++;
        else             pp = pos2++;
        entries[pp] = ent;
    }
    __syncthreads();

    // ---- 4. Gather + dot + exp, phase by phase (free-running) ----
    const float4* x4 = reinterpret_cast<const float4*>(x + b * D_SZ);
    const float4 xx0 = x4[0 * 8 + o];
    const float4 xx1 = x4[1 * 8 + o];
    const float4 xx2 = x4[2 * 8 + o];
    const float4 xx3 = x4[3 * 8 + o];

    const uint32_t tc[NPH] = { t0, t1, t2 };
    float wsum = 0.0f;
    uint32_t lo = 0;
    #pragma unroll
    for (int p = 0; p < NPH; p++) {
        const uint32_t hi = lo + tc[p];
        for (uint32_t e0 = lo + (uint32_t)warp * 4u; e0 < hi; e0 += WARPS * 4u) {
            const uint32_t e = e0 + (uint32_t)r;
            const bool valid = (e < hi);
            float acc = 0.0f;
            uint32_t kl = 0;
            if (valid) {
                const uint32_t ent = entries[e];
                const uint32_t row = ent >> 11;
                kl = ent & 2047u;
                const float4* m4 = reinterpret_cast<const float4*>(memory + (size_t)row * D_SZ);
                const float4 w0 = m4[0 * 8 + o];
                const float4 w1 = m4[1 * 8 + o];
                const float4 w2 = m4[2 * 8 + o];
                const float4 w3 = m4[3 * 8 + o];
                acc  = w0.x * xx0.x + w0.y * xx0.y + w0.z * xx0.z + w0.w * xx0.w;
                acc += w1.x * xx1.x + w1.y * xx1.y + w1.z * xx1.z + w1.w * xx1.w;
                acc += w2.x * xx2.x + w2.y * xx2.y + w2.z * xx2.z + w2.w * xx2.w;
                acc += w3.x * xx3.x + w3.y * xx3.y + w3.z * xx3.z + w3.w * xx3.w;
            }
            // converge, then reduce the 8 lanes of each row (4 rows at once)
            acc += __shfl_xor_sync(0xffffffffu, acc, 1);
            acc += __shfl_xor_sync(0xffffffffu, acc, 2);
            acc += __shfl_xor_sync(0xffffffffu, acc, 4);
            if (o == 0 && valid) {
                const float s = __expf(acc * INV_T);
                sout[kl] = s;
                wsum += s;
            }
        }
        lo = hi;
    }

    // ---- 5. Coalesced flush (plain stores: keep `out` L2-resident) ----
    __syncthreads();
    float4* ob4 = reinterpret_cast<float4*>(out + (size_t)b * K_SZ + kbase);
    const float4* so4 = reinterpret_cast<const float4*>(sout);
    #pragma unroll
    for (int i = 0; i < KRANGE / 4 / TPB; i++)      // 2 iterations
        ob4[t + i * TPB] = so4[t + i * TPB];

    // ---- 6. Block partial (fixed order) + ticket ----
    #pragma unroll
    for (int s = 16; s > 0; s >>= 1)
        wsum += __shfl_xor_sync(0xffffffffu, wsum, s);
    if (lane == 0) ssum[warp] = wsum;
    __syncthreads();
    if (t == 0) {
        float acc = 0.0f;
        #pragma unroll
        for (int w = 0; w < WARPS; w++) acc += ssum[w];
        g_partials[blockIdx.x] = acc;
        __threadfence();
        const unsigned int tk = atomicAdd(&g_ticket, 1u);
        s_last = (tk == NBLK - 1);
    }
    __syncthreads();

    // ---- 7. Last block: fixed-order double reduce of 512 partials ----
    if (s_last) {
        double acc = (double)g_partials[t] + (double)g_partials[t + TPB];
        dsh[t] = acc;
        __syncthreads();
        for (int s = TPB / 2; s > 0; s >>= 1) {
            if (t < s) dsh[t] += dsh[t + s];
            __syncthreads();
        }
        if (t == 0) {
            // Z = (sum / (B*K)) * N ; scale = 1/Z — double avoids fp32
            // overflow (sum ~ 1e31; sum*N would be inf in fp32).
            const double sum = dsh[0];
            g_scale = (float)(((double)B_SZ * (double)K_SZ) /
                              (sum * (double)N_SZ));
            g_ticket = 0u;             // reset for graph replay
            __threadfence();
        }
    }
}

// out: 262144 float4s -> 1024 blocks x 256 threads x 1 float4.
// Reads hit L2 (scores flushed plain); writes stream out.
__global__ __launch_bounds__(256)
void nce_norm_kernel(float* __restrict__ out) {
    const float s = g_scale;
    const int i = blockIdx.x * blockDim.x + threadIdx.x;
    float4* o = reinterpret_cast<float4*>(out);
    float4 v = o[i];
    v.x *= s; v.y *= s; v.z *= s; v.w *= s;
    __stcs(&o[i], v);
}

extern "C" void kernel_launch(void* const* d_in, const int* in_sizes, int n_in,
                              void* d_out, int out_size) {
    const float* x      = (const float*)d_in[0];
    const int*   y      = (const int*)d_in[1];
    const int*   idx    = (const int*)d_in[2];
    const float* memory = (const float*)d_in[3];
    float* out = (float*)d_out;

    nce_scores_kernel<<<NBLK, TPB>>>(x, y, idx, memory, out);
    const int nvec4 = (B_SZ * K_SZ) / 4;   // 262144
    nce_norm_kernel<<<nvec4 / 256, 256>>>(out);
}

// round 16
// speedup vs baseline: 1.4561x; 1.0974x over previous
#include <cuda_runtime.h>
#include <cuda_bf16.h>
#include <cstdint>

// NCEAverage: out[b,k] = exp(dot(memory[idx'[b,k]], x[b]) / T) / Z
// idx'[b,0] = y[b];  Z = mean(out_unnorm) * N
// B=256, K=4096, D=128, N=1e6, T=0.07
//
// Phase-partitioned gather (4 phases, free-running — measured optimum:
// 3->72.4us, 4->72.2, 6->76.3, 8->80.2; pacing/gates always lose).
// 512 blocks (single resident wave) each own one (b, 2048-k) range and
// deterministically bucket their 2048 row indices by row>>18; the chip
// sweeps slices roughly together so duplicate rows hit L2 instead of DRAM.
// Gather loop unrolled x2: 8 rows (8 independent LDG.128 per lane) in
// flight per warp-iteration to cover L2/DRAM latency.
// Scores staged in SMEM, flushed with plain stores (out stays L2-resident
// for the norm kernel). Z: ticket + last-block fixed-order double reduce.

#define B_SZ 256
#define K_SZ 4096
#define D_SZ 128
#define N_SZ 1000000
#define INV_T (1.0f / 0.07f)

#define TPB 256
#define WARPS 8
#define KRANGE 2048                    // k's per block
#define NBLK (B_SZ * K_SZ / KRANGE)    // 512 blocks = one resident wave
#define EPT (KRANGE / TPB)             // 8 indices per thread
#define PHASE_SHIFT 18                 // 4 phases of <=262144 rows

__device__ float        g_partials[NBLK];
__device__ float        g_scale;
__device__ unsigned int g_ticket;      // zero-init; last block resets

__global__ __launch_bounds__(TPB, 4)
void nce_scores_kernel(const float* __restrict__ x,
                       const int* __restrict__ y,
                       const int* __restrict__ idx,
                       const float* __restrict__ memory,
                       float* __restrict__ out) {
    __shared__ uint32_t           entries[KRANGE];   // (row<<11)|k_local
    __shared__ float              sout[KRANGE];      // staged scores
    __shared__ unsigned long long wtot[WARPS];
    __shared__ float              ssum[WARPS];
    __shared__ double             dsh[TPB];
    __shared__ bool               s_last;

    const int t     = threadIdx.x;
    const int lane  = t & 31;
    const int warp  = t >> 5;
    const int o     = lane & 7;        // octet within row
    const int r     = lane >> 3;       // which of 4 rows in a group
    const int b     = blockIdx.x >> 1;
    const int kbase = (blockIdx.x & 1) * KRANGE;

    // ---- 1. Load indices, count per phase (thread-major canonical order) ----
    const int* idx_b = idx + (size_t)b * K_SZ + kbase;
    uint32_t myrow[EPT];
    uint32_t c0 = 0, c1 = 0, c2 = 0, c3 = 0;
    #pragma unroll
    for (int j = 0; j < EPT; j++) {
        const int kl = j * TPB + t;
        const uint32_t row = (uint32_t)((kbase + kl == 0) ? y[b] : idx_b[kl]);
        myrow[j] = row;
        const uint32_t p = row >> PHASE_SHIFT;
        c0 += (p == 0); c1 += (p == 1); c2 += (p == 2); c3 += (p == 3);
    }

    // ---- 2. Scan of 4x16-bit packed counts: warp shfl scan + cross-warp ----
    const unsigned long long v = (unsigned long long)c0
                               | ((unsigned long long)c1 << 16)
                               | ((unsigned long long)c2 << 32)
                               | ((unsigned long long)c3 << 48);
    unsigned long long ws = v;                       // warp-inclusive scan
    #pragma unroll
    for (int off = 1; off < 32; off <<= 1) {
        const unsigned long long n = __shfl_up_sync(0xffffffffu, ws, off);
        if (lane >= off) ws += n;
    }
    if (lane == 31) wtot[warp] = ws;
    __syncthreads();
    unsigned long long wpre = 0, tot = 0;
    #pragma unroll
    for (int w = 0; w < WARPS; w++) {               // fixed order, tiny
        const unsigned long long wv = wtot[w];
        if (w < warp) wpre += wv;
        tot += wv;
    }
    const unsigned long long excl = ws + wpre - v;

    const uint32_t t0 = (uint32_t)(tot      ) & 0xffffu;
    const uint32_t t1 = (uint32_t)(tot >> 16) & 0xffffu;
    const uint32_t t2 = (uint32_t)(tot >> 32) & 0xffffu;
    const uint32_t t3 = (uint32_t)(tot >> 48) & 0xffffu;

    uint32_t pos0 =                ((uint32_t)(excl      ) & 0xffffu);
    uint32_t pos1 = t0           + ((uint32_t)(excl >> 16) & 0xffffu);
    uint32_t pos2 = t0 + t1      + ((uint32_t)(excl >> 32) & 0xffffu);
    uint32_t pos3 = t0 + t1 + t2 + ((uint32_t)(excl >> 48) & 0xffffu);

    // ---- 3. Deterministic scatter into phase buckets ----
    #pragma unroll
    for (int j = 0; j < EPT; j++) {
        const uint32_t row = myrow[j];
        const uint32_t p   = row >> PHASE_SHIFT;
        const uint32_t ent = (row << 11) | (uint32_t)(j * TPB + t);
        uint32_t pp;
        if      (p == 0) pp = pos0++;
        else if (p == 1) pp = pos1++;
        else if (p == 2) pp = pos2++;
        else             pp = pos3++;
        entries[pp] = ent;
    }
    __syncthreads();

    // ---- 4. Gather + dot + exp, phase by phase; 8 rows in flight/warp ----
    const float4* x4 = reinterpret_cast<const float4*>(x + b * D_SZ);
    const float4 xx0 = x4[0 * 8 + o];
    const float4 xx1 = x4[1 * 8 + o];
    const float4 xx2 = x4[2 * 8 + o];
    const float4 xx3 = x4[3 * 8 + o];

    const uint32_t tc[4] = { t0, t1, t2, t3 };
    float wsum = 0.0f;
    uint32_t lo = 0;
    #pragma unroll 1
    for (int p = 0; p < 4; p++) {
        const uint32_t hi = lo + tc[p];
        uint32_t e0 = lo + (uint32_t)warp * 8u;
        // main: two 4-row groups per iteration (8 independent loads)
        for (; e0 + 8u <= hi; e0 += WARPS * 8u) {
            bool run2 = true;
            const uint32_t eA = e0 + (uint32_t)r;
            const uint32_t eB = e0 + 4u + (uint32_t)r;
            const uint32_t entA = entries[eA];
            const uint32_t entB = entries[eB];
            const uint32_t rowA = entA >> 11;
            const uint32_t rowB = entB >> 11;
            const float4* mA = reinterpret_cast<const float4*>(memory + (size_t)rowA * D_SZ);
            const float4* mB = reinterpret_cast<const float4*>(memory + (size_t)rowB * D_SZ);
            const float4 a0 = mA[0 * 8 + o];
            const float4 a1 = mA[1 * 8 + o];
            const float4 a2 = mA[2 * 8 + o];
            const float4 a3 = mA[3 * 8 + o];
            const float4 b0 = mB[0 * 8 + o];
            const float4 b1 = mB[1 * 8 + o];
            const float4 b2 = mB[2 * 8 + o];
            const float4 b3 = mB[3 * 8 + o];

            float accA, accB;
            accA  = a0.x * xx0.x + a0.y * xx0.y + a0.z * xx0.z + a0.w * xx0.w;
            accB  = b0.x * xx0.x + b0.y * xx0.y + b0.z * xx0.z + b0.w * xx0.w;
            accA += a1.x * xx1.x + a1.y * xx1.y + a1.z * xx1.z + a1.w * xx1.w;
            accB += b1.x * xx1.x + b1.y * xx1.y + b1.z * xx1.z + b1.w * xx1.w;
            accA += a2.x * xx2.x + a2.y * xx2.y + a2.z * xx2.z + a2.w * xx2.w;
            accB += b2.x * xx2.x + b2.y * xx2.y + b2.z * xx2.z + b2.w * xx2.w;
            accA += a3.x * xx3.x + a3.y * xx3.y + a3.z * xx3.z + a3.w * xx3.w;
            accB += b3.x * xx3.x + b3.y * xx3.y + b3.z * xx3.z + b3.w * xx3.w;

            #pragma unroll
            for (int s = 1; s <= 4; s <<= 1) {
                accA += __shfl_xor_sync(0xffffffffu, accA, s);
                accB += __shfl_xor_sync(0xffffffffu, accB, s);
            }
            if (o == 0) {
                const float sA = __expf(accA * INV_T);
                const float sB = __expf(accB * INV_T);
                sout[entA & 2047u] = sA;
                sout[entB & 2047u] = sB;
                wsum += sA + sB;
            }
            (void)run2;
        }
        // tail: single 4-row group with masking
        for (; e0 < hi; e0 += 4u) {
            const uint32_t e = e0 + (uint32_t)r;
            const bool valid = (e < hi);
            float acc = 0.0f;
            uint32_t kl = 0;
            if (valid) {
                const uint32_t ent = entries[e];
                const uint32_t row = ent >> 11;
                kl = ent & 2047u;
                const float4* m4 = reinterpret_cast<const float4*>(memory + (size_t)row * D_SZ);
                const float4 w0 = m4[0 * 8 + o];
                const float4 w1 = m4[1 * 8 + o];
                const float4 w2 = m4[2 * 8 + o];
                const float4 w3 = m4[3 * 8 + o];
                acc  = w0.x * xx0.x + w0.y * xx0.y + w0.z * xx0.z + w0.w * xx0.w;
                acc += w1.x * xx1.x + w1.y * xx1.y + w1.z * xx1.z + w1.w * xx1.w;
                acc += w2.x * xx2.x + w2.y * xx2.y + w2.z * xx2.z + w2.w * xx2.w;
                acc += w3.x * xx3.x + w3.y * xx3.y + w3.z * xx3.z + w3.w * xx3.w;
            }
            acc += __shfl_xor_sync(0xffffffffu, acc, 1);
            acc += __shfl_xor_sync(0xffffffffu, acc, 2);
            acc += __shfl_xor_sync(0xffffffffu, acc, 4);
            if (o == 0 && valid) {
                const float s = __expf(acc * INV_T);
                sout[kl] = s;
                wsum += s;
            }
        }
        lo = hi;
    }

    // ---- 5. Coalesced flush (plain stores: keep `out` L2-resident) ----
    __syncthreads();
    float4* ob4 = reinterpret_cast<float4*>(out + (size_t)b * K_SZ + kbase);
    const float4* so4 = reinterpret_cast<const float4*>(sout);
    #pragma unroll
    for (int i = 0; i < KRANGE / 4 / TPB; i++)      // 2 iterations
        ob4[t + i * TPB] = so4[t + i * TPB];

    // ---- 6. Block partial (fixed order) + ticket ----
    #pragma unroll
    for (int s = 16; s > 0; s >>= 1)
        wsum += __shfl_xor_sync(0xffffffffu, wsum, s);
    if (lane == 0) ssum[warp] = wsum;
    __syncthreads();
    if (t == 0) {
        float acc = 0.0f;
        #pragma unroll
        for (int w = 0; w < WARPS; w++) acc += ssum[w];
        g_partials[blockIdx.x] = acc;
        __threadfence();
        const unsigned int tk = atomicAdd(&g_ticket, 1u);
        s_last = (tk == NBLK - 1);
    }
    __syncthreads();

    // ---- 7. Last block: fixed-order double reduce of 512 partials ----
    if (s_last) {
        double acc = (double)g_partials[t] + (double)g_partials[t + TPB];
        dsh[t] = acc;
        __syncthreads();
        for (int s = TPB / 2; s > 0; s >>= 1) {
            if (t < s) dsh[t] += dsh[t + s];
            __syncthreads();
        }
        if (t == 0) {
            // Z = (sum / (B*K)) * N ; scale = 1/Z — double avoids fp32
            // overflow (sum ~ 1e31; sum*N would be inf in fp32).
            const double sum = dsh[0];
            g_scale = (float)(((double)B_SZ * (double)K_SZ) /
                              (sum * (double)N_SZ));
            g_ticket = 0u;             // reset for graph replay
            __threadfence();
        }
    }
}

// out: 262144 float4s -> 1024 blocks x 256 threads x 1 float4.
// Reads hit L2 (scores flushed plain); writes stream out.
__global__ __launch_bounds__(256)
void nce_norm_kernel(float* __restrict__ out) {
    const float s = g_scale;
    const int i = blockIdx.x * blockDim.x + threadIdx.x;
    float4* o = reinterpret_cast<float4*>(out);
    float4 v = o[i];
    v.x *= s; v.y *= s; v.z *= s; v.w *= s;
    __stcs(&o[i], v);
}

extern "C" void kernel_launch(void* const* d_in, const int* in_sizes, int n_in,
                              void* d_out, int out_size) {
    const float* x      = (const float*)d_in[0];
    const int*   y      = (const int*)d_in[1];
    const int*   idx    = (const int*)d_in[2];
    const float* memory = (const float*)d_in[3];
    float* out = (float*)d_out;

    nce_scores_kernel<<<NBLK, TPB>>>(x, y, idx, memory, out);
    const int nvec4 = (B_SZ * K_SZ) / 4;   // 262144
    nce_norm_kernel<<<nvec4 / 256, 256>>>(out);
}